// round 13
// baseline (speedup 1.0000x reference)
#include <cuda_runtime.h>
#include <math.h>

#define NNODES 100000
#define NEDGES 1600000

// ---------------- scratch (static device globals; no allocations) ----------------
__device__ float g_agg [(size_t)NNODES * 192];
__device__ float g_gi  [(size_t)NNODES * 192];
__device__ float g_gh  [(size_t)NNODES * 192];
__device__ float g_out [(size_t)NNODES * 64];
__device__ float g_h   [(size_t)NNODES * 64];
__device__ float g_swh [(size_t)NNODES * 64];
__device__ float g_tmp [(size_t)NNODES * 64];
__device__ float g_stats[512];
__device__ float g_scale[4 * 64];
__device__ float g_shift[4 * 64];
__device__ int   g_rowptr[NNODES + 1];
__device__ int   g_cursor[NNODES];
__device__ int   g_ekey [NEDGES];
__device__ float g_enorm[NEDGES];
__device__ int   g_bsums[128];
// packed weights: 12 units x 2048 uints (hi, lo). unit order:
// emb=0(1), relW=1..3, Wih=4..6, Whh=7..9, aW1=10, bW1=11
__device__ unsigned int g_whi[12 * 2048];
__device__ unsigned int g_wlo[12 * 2048];

__device__ __forceinline__ float sigm(float x) { return 1.0f / (1.0f + expf(-x)); }

__device__ __forceinline__ unsigned int packbf(float lo, float hi) {
    unsigned int r;
    asm("cvt.rn.bf16x2.f32 %0, %1, %2;" : "=r"(r) : "f"(hi), "f"(lo));
    return r;
}

#define MMA_BF16(c0, c1, c2, c3, a0, a1, a2, a3, b0, b1)                       \
    asm("mma.sync.aligned.m16n8k16.row.col.f32.bf16.bf16.f32 "                 \
        "{%0,%1,%2,%3}, {%4,%5,%6,%7}, {%8,%9}, {%0,%1,%2,%3};"                \
        : "+f"(c0), "+f"(c1), "+f"(c2), "+f"(c3)                               \
        : "r"(a0), "r"(a1), "r"(a2), "r"(a3), "r"(b0), "r"(b1))

// ---------------- weight pre-pack: one unit = 64x64 fp32 -> [n][kpair] hi/lo ----
__global__ void k_packW(const float* __restrict__ W, int transW,
                        int w_y_stride, int w_k_stride, int nkb,
                        unsigned int* __restrict__ hi, unsigned int* __restrict__ lo) {
    int u = blockIdx.x;
    int y = u / nkb, kb = u % nkb;
    const float* Wb = W + (size_t)y * w_y_stride + (size_t)kb * w_k_stride;
    for (int i = threadIdx.x; i < 2048; i += 256) {
        int n = i >> 5, p = i & 31;
        float f0, f1;
        if (transW) { f0 = Wb[n * 64 + 2 * p];   f1 = Wb[n * 64 + 2 * p + 1]; }
        else        { f0 = Wb[(2 * p) * 64 + n]; f1 = Wb[(2 * p + 1) * 64 + n]; }
        unsigned int h = packbf(f0, f1);
        float la = f0 - __uint_as_float(h << 16);
        float lb = f1 - __uint_as_float(h & 0xffff0000u);
        hi[(size_t)blockIdx.x * 2048 + i] = h;
        lo[(size_t)blockIdx.x * 2048 + i] = packbf(la, lb);
    }
}

// ---------------- CSR build ----------------
__global__ void k_count(const int* __restrict__ dst, int* __restrict__ cnt) {
    int e = blockIdx.x * blockDim.x + threadIdx.x;
    if (e < NEDGES) atomicAdd(&cnt[dst[e]], 1);
}

__global__ void k_scanA(const int* __restrict__ cnt, int* __restrict__ bsums) {
    __shared__ int sh[1024];
    int i = blockIdx.x * 1024 + threadIdx.x;
    sh[threadIdx.x] = (i < NNODES) ? cnt[i] : 0;
    __syncthreads();
    for (int off = 512; off > 0; off >>= 1) {
        if (threadIdx.x < off) sh[threadIdx.x] += sh[threadIdx.x + off];
        __syncthreads();
    }
    if (threadIdx.x == 0) bsums[blockIdx.x] = sh[0];
}

__global__ void k_scanB(int* __restrict__ bsums, int nb, int* __restrict__ rowptr) {
    __shared__ int sh[128];
    int t = threadIdx.x;
    int orig = (t < nb) ? bsums[t] : 0;
    sh[t] = orig;
    __syncthreads();
    for (int off = 1; off < 128; off <<= 1) {
        int v = (t >= off) ? sh[t - off] : 0;
        __syncthreads();
        sh[t] += v;
        __syncthreads();
    }
    if (t < nb) bsums[t] = sh[t] - orig;
    if (t == 0) rowptr[NNODES] = NEDGES;
}

__global__ void k_scanC(int* __restrict__ cnt, const int* __restrict__ bsums,
                        int* __restrict__ rowptr, int* __restrict__ cursor) {
    __shared__ int sh[1024];
    int i = blockIdx.x * 1024 + threadIdx.x;
    int orig = (i < NNODES) ? cnt[i] : 0;
    sh[threadIdx.x] = orig;
    __syncthreads();
    for (int off = 1; off < 1024; off <<= 1) {
        int v = (threadIdx.x >= off) ? sh[threadIdx.x - off] : 0;
        __syncthreads();
        sh[threadIdx.x] += v;
        __syncthreads();
    }
    if (i < NNODES) {
        int start = bsums[blockIdx.x] + sh[threadIdx.x] - orig;
        rowptr[i] = start;
        cursor[i] = start;
    }
}

__global__ void k_scatter(const int* __restrict__ dst, const int* __restrict__ src,
                          const int* __restrict__ rel, const float* __restrict__ norm,
                          int* __restrict__ cursor,
                          int* __restrict__ ekey, float* __restrict__ enorm) {
    int e = blockIdx.x * blockDim.x + threadIdx.x;
    if (e < NEDGES) {
        int pos = atomicAdd(&cursor[dst[e]], 1);
        ekey[pos]  = (src[e] << 2) | rel[e];
        enorm[pos] = norm[e];
    }
}

// ---------------- tensor-core matmul: 128 nodes x 64 cols, pre-packed W --------
// 256 threads = 8 warps; warp w: rows w*16..w*16+15, ALL 64 cols (8 n-tiles).
// A staged in smem (hi/lo bf16x2, stride 36, conflict-free). W fragments read
// directly from pre-packed global (L1/L2 resident).
// Split: D ~= AhBh + AhBl + AlBh.
template <int KB>
__global__ __launch_bounds__(256) void k_mm(
    const float* __restrict__ A, int a_stride,
    const unsigned int* __restrict__ Whig, const unsigned int* __restrict__ Wlog,
    const float* __restrict__ bias, int bias_blk,
    const float* __restrict__ in_scale, const float* __restrict__ in_shift, int in_act,
    float* __restrict__ C, int c_stride,
    float* __restrict__ stats)
{
    __shared__ unsigned int Ahi[128 * 36], Alo[128 * 36];   // 36,864 B

    int tid  = threadIdx.x;
    int warp = tid >> 5, lane = tid & 31;
    int gid  = lane >> 2, tig = lane & 3;
    int nbase = blockIdx.x * 128;

    float acc[8][4];
#pragma unroll
    for (int nt = 0; nt < 8; nt++)
#pragma unroll
        for (int q = 0; q < 4; q++) acc[nt][q] = 0.f;

#pragma unroll
    for (int kb = 0; kb < KB; kb++) {
        if (kb > 0) __syncthreads();

        // ---- stage A (128 x 64 fp32 -> hi/lo bf16x2 pairs) ----
        for (int i = tid; i < 2048; i += 256) {
            int r = i >> 4, c4 = i & 15;
            float4 v = make_float4(0.f, 0.f, 0.f, 0.f);
            int gn = nbase + r;
            if (gn < NNODES)
                v = reinterpret_cast<const float4*>(A + (size_t)gn * a_stride + kb * 64)[c4];
            if (in_act) {
                int c = c4 * 4;
                v.x = v.x * in_scale[c]     + in_shift[c];
                v.y = v.y * in_scale[c + 1] + in_shift[c + 1];
                v.z = v.z * in_scale[c + 2] + in_shift[c + 2];
                v.w = v.w * in_scale[c + 3] + in_shift[c + 3];
            }
            unsigned int h0 = packbf(v.x, v.y);
            unsigned int h1 = packbf(v.z, v.w);
            float l0a = v.x - __uint_as_float(h0 << 16);
            float l0b = v.y - __uint_as_float(h0 & 0xffff0000u);
            float l1a = v.z - __uint_as_float(h1 << 16);
            float l1b = v.w - __uint_as_float(h1 & 0xffff0000u);
            int base = r * 36 + c4 * 2;
            Ahi[base]     = h0;
            Ahi[base + 1] = h1;
            Alo[base]     = packbf(l0a, l0b);
            Alo[base + 1] = packbf(l1a, l1b);
        }
        __syncthreads();

        const unsigned int* Hb = Whig + (size_t)(blockIdx.y * KB + kb) * 2048;
        const unsigned int* Lb = Wlog + (size_t)(blockIdx.y * KB + kb) * 2048;

        int r0 = warp * 16 + gid;
#pragma unroll
        for (int ks = 0; ks < 4; ks++) {
            int kp = ks * 8;
            unsigned int ah0 = Ahi[r0 * 36 + kp + tig];
            unsigned int ah1 = Ahi[(r0 + 8) * 36 + kp + tig];
            unsigned int ah2 = Ahi[r0 * 36 + kp + tig + 4];
            unsigned int ah3 = Ahi[(r0 + 8) * 36 + kp + tig + 4];
            unsigned int al0 = Alo[r0 * 36 + kp + tig];
            unsigned int al1 = Alo[(r0 + 8) * 36 + kp + tig];
            unsigned int al2 = Alo[r0 * 36 + kp + tig + 4];
            unsigned int al3 = Alo[(r0 + 8) * 36 + kp + tig + 4];
#pragma unroll
            for (int nt = 0; nt < 8; nt++) {
                int n0 = nt * 8 + gid;
                unsigned int bh0 = Hb[n0 * 32 + kp + tig];
                unsigned int bh1 = Hb[n0 * 32 + kp + tig + 4];
                unsigned int bl0 = Lb[n0 * 32 + kp + tig];
                unsigned int bl1 = Lb[n0 * 32 + kp + tig + 4];
                MMA_BF16(acc[nt][0], acc[nt][1], acc[nt][2], acc[nt][3],
                         ah0, ah1, ah2, ah3, bh0, bh1);
                MMA_BF16(acc[nt][0], acc[nt][1], acc[nt][2], acc[nt][3],
                         ah0, ah1, ah2, ah3, bl0, bl1);
                MMA_BF16(acc[nt][0], acc[nt][1], acc[nt][2], acc[nt][3],
                         al0, al1, al2, al3, bh0, bh1);
            }
        }
    }

    // ---- epilogue: bias, store, stats ----
    float s_loc[16], q_loc[16];
#pragma unroll
    for (int e = 0; e < 16; e++) { s_loc[e] = 0.f; q_loc[e] = 0.f; }

    int row0 = nbase + warp * 16 + gid;
    int row1 = row0 + 8;
#pragma unroll
    for (int nt = 0; nt < 8; nt++) {
        int lcol = nt * 8 + 2 * tig;
        int gcol = blockIdx.y * 64 + lcol;
        float bv0 = 0.f, bv1 = 0.f;
        if (bias) {
            const float* bb = bias + blockIdx.y * bias_blk;
            bv0 = bb[lcol]; bv1 = bb[lcol + 1];
        }
        float o00 = acc[nt][0] + bv0, o01 = acc[nt][1] + bv1;
        float o10 = acc[nt][2] + bv0, o11 = acc[nt][3] + bv1;
        if (row0 < NNODES) {
            *reinterpret_cast<float2*>(C + (size_t)row0 * c_stride + gcol) =
                make_float2(o00, o01);
            s_loc[nt * 2]     += o00; q_loc[nt * 2]     += o00 * o00;
            s_loc[nt * 2 + 1] += o01; q_loc[nt * 2 + 1] += o01 * o01;
        }
        if (row1 < NNODES) {
            *reinterpret_cast<float2*>(C + (size_t)row1 * c_stride + gcol) =
                make_float2(o10, o11);
            s_loc[nt * 2]     += o10; q_loc[nt * 2]     += o10 * o10;
            s_loc[nt * 2 + 1] += o11; q_loc[nt * 2 + 1] += o11 * o11;
        }
    }

    if (stats) {
        __syncthreads();
        float* ssum = reinterpret_cast<float*>(Ahi);
        float* ssq  = ssum + 64;
        if (tid < 128) ssum[tid] = 0.f;
        __syncthreads();
#pragma unroll
        for (int nt = 0; nt < 8; nt++) {
            int lcol = nt * 8 + 2 * tig;
            atomicAdd(&ssum[lcol],     s_loc[nt * 2]);
            atomicAdd(&ssum[lcol + 1], s_loc[nt * 2 + 1]);
            atomicAdd(&ssq [lcol],     q_loc[nt * 2]);
            atomicAdd(&ssq [lcol + 1], q_loc[nt * 2 + 1]);
        }
        __syncthreads();
        if (tid < 64) {
            atomicAdd(&stats[tid], ssum[tid]);
            atomicAdd(&stats[64 + tid], ssq[tid]);
        }
    }
}

// ---------------- BN helpers ----------------
__global__ void k_finalize(const float* __restrict__ stats, const float* __restrict__ gamma,
                           const float* __restrict__ beta, float* __restrict__ scale,
                           float* __restrict__ shift) {
    int k = threadIdx.x;
    const float invN = 1.0f / (float)NNODES;
    float mean = stats[k] * invN;
    float var = stats[64 + k] * invN - mean * mean;
    float sc = gamma[k] * rsqrtf(var + 1e-5f);
    scale[k] = sc;
    shift[k] = beta[k] - mean * sc;
}

__global__ void k_stats64(const float* __restrict__ X, float* __restrict__ stats) {
    __shared__ float ssum[64], ssq[64];
    int k = threadIdx.x, ty = threadIdx.y;
    if (ty == 0) { ssum[k] = 0.f; ssq[k] = 0.f; }
    __syncthreads();
    float s = 0.f, q = 0.f;
    for (int n = blockIdx.x * 4 + ty; n < NNODES; n += gridDim.x * 4) {
        float v = X[(size_t)n * 64 + k];
        s += v; q += v * v;
    }
    atomicAdd(&ssum[k], s); atomicAdd(&ssq[k], q);
    __syncthreads();
    if (ty == 0) { atomicAdd(&stats[k], ssum[k]); atomicAdd(&stats[64 + k], ssq[k]); }
}

// ---------------- rel-split edge aggregation (warp per node) ----------------
template <int AFF>
__global__ void k_aggregate(const float* __restrict__ in, const int* __restrict__ rowptr,
                            const int* __restrict__ ekey, const float* __restrict__ enorm,
                            const float* __restrict__ scale, const float* __restrict__ shift,
                            float* __restrict__ agg) {
    int node = (blockIdx.x * blockDim.x + threadIdx.x) >> 5;
    int lane = threadIdx.x & 31;
    if (node >= NNODES) return;
    float sc0 = 1.f, sc1 = 1.f, sf0 = 0.f, sf1 = 0.f;
    if (AFF) { sc0 = scale[lane]; sc1 = scale[lane + 32];
               sf0 = shift[lane]; sf1 = shift[lane + 32]; }
    int beg = rowptr[node], end = rowptr[node + 1];
    float a00 = 0.f, a01 = 0.f, a10 = 0.f, a11 = 0.f, a20 = 0.f, a21 = 0.f;
    for (int e = beg; e < end; ++e) {
        int k0 = ekey[e];
        float w = enorm[e];
        const float* row = in + (size_t)(k0 >> 2) * 64;
        float v0 = row[lane], v1 = row[lane + 32];
        if (AFF) {
            v0 = fmaxf(v0 * sc0 + sf0, 0.f);
            v1 = fmaxf(v1 * sc1 + sf1, 0.f);
        }
        int r = k0 & 3;
        if (r == 0)      { a00 = fmaf(v0, w, a00); a01 = fmaf(v1, w, a01); }
        else if (r == 1) { a10 = fmaf(v0, w, a10); a11 = fmaf(v1, w, a11); }
        else             { a20 = fmaf(v0, w, a20); a21 = fmaf(v1, w, a21); }
    }
    float* o = agg + (size_t)node * 192;
    o[lane] = a00;       o[lane + 32] = a01;
    o[64 + lane] = a10;  o[96 + lane] = a11;
    o[128 + lane] = a20; o[160 + lane] = a21;
}

// ---------------- GRU gate fusion ----------------
__global__ void k_gates0(const float* __restrict__ gi, const float* __restrict__ bhh,
                         float* __restrict__ h) {
    size_t idx = (size_t)blockIdx.x * blockDim.x + threadIdx.x;
    if (idx >= (size_t)NNODES * 64) return;
    int n = (int)(idx >> 6), k = (int)(idx & 63);
    size_t b = (size_t)n * 192;
    float r = sigm(gi[b + k] + bhh[k]);
    float z = sigm(gi[b + 64 + k] + bhh[64 + k]);
    float nn = tanhf(gi[b + 128 + k] + r * bhh[128 + k]);
    h[idx] = (1.0f - z) * nn;
}

__global__ void k_gates(const float* __restrict__ gi, const float* __restrict__ gh,
                        float* __restrict__ h) {
    size_t idx = (size_t)blockIdx.x * blockDim.x + threadIdx.x;
    if (idx >= (size_t)NNODES * 64) return;
    int n = (int)(idx >> 6), k = (int)(idx & 63);
    size_t b = (size_t)n * 192;
    float r = sigm(gi[b + k] + gh[b + k]);
    float z = sigm(gi[b + 64 + k] + gh[b + 64 + k]);
    float nn = tanhf(gi[b + 128 + k] + r * gh[b + 128 + k]);
    float hv = h[idx];
    h[idx] = (1.0f - z) * nn + z * hv;
}

// ---------------- head output: relu(BN(tmp)) @ W2.T + b2 ----------------
template <int KO>
__global__ void k_head(const float* __restrict__ X, const float* __restrict__ scale,
                       const float* __restrict__ shift, const float* __restrict__ W2,
                       const float* __restrict__ b2, float* __restrict__ out) {
    __shared__ float Wsh[KO * 65];
    __shared__ float sc[64], sf[64];
    int tid = threadIdx.x;
    for (int i = tid; i < KO * 64; i += 256) {
        int k = i >> 6, d = i & 63;
        Wsh[k * 65 + d] = W2[i];
    }
    if (tid < 64) { sc[tid] = scale[tid]; sf[tid] = shift[tid]; }
    __syncthreads();
    int warp = tid >> 5, lane = tid & 31;
    int n = blockIdx.x * 8 + warp;
    if (n >= NNODES) return;
    float acc = (lane < KO) ? b2[lane] : 0.f;
    const float* row = X + (size_t)n * 64;
    for (int d = 0; d < 64; d++) {
        float x = fmaxf(row[d] * sc[d] + sf[d], 0.f);
        if (lane < KO) acc = fmaf(x, Wsh[lane * 65 + d], acc);
    }
    if (lane < KO) out[(size_t)n * KO + lane] = acc;
}

// ---------------- launch ----------------
extern "C" void kernel_launch(void* const* d_in, const int* in_sizes, int n_in,
                              void* d_out, int out_size) {
    const float* v      = (const float*)d_in[0];
    const int*   src    = (const int*)d_in[1];
    const int*   dst    = (const int*)d_in[2];
    const int*   rel    = (const int*)d_in[3];
    const float* norm   = (const float*)d_in[4];
    const float* emb_W  = (const float*)d_in[5];
    const float* emb_b  = (const float*)d_in[6];
    const float* emb_g  = (const float*)d_in[7];
    const float* emb_be = (const float*)d_in[8];
    const float* relW   = (const float*)d_in[9];
    const float* Wih    = (const float*)d_in[10];
    const float* Whh    = (const float*)d_in[11];
    const float* bih    = (const float*)d_in[12];
    const float* bhh    = (const float*)d_in[13];
    const float* ker_g  = (const float*)d_in[14];
    const float* ker_be = (const float*)d_in[15];
    const float* aW1 = (const float*)d_in[16];
    const float* ab1 = (const float*)d_in[17];
    const float* ag  = (const float*)d_in[18];
    const float* abe = (const float*)d_in[19];
    const float* aW2 = (const float*)d_in[20];
    const float* ab2 = (const float*)d_in[21];
    const float* bW1 = (const float*)d_in[22];
    const float* bb1 = (const float*)d_in[23];
    const float* bg  = (const float*)d_in[24];
    const float* bbe = (const float*)d_in[25];
    const float* bW2 = (const float*)d_in[26];
    const float* bb2 = (const float*)d_in[27];
    float* out = (float*)d_out;

    float *p_agg, *p_gi, *p_gh, *p_out, *p_h, *p_swh, *p_tmp, *p_stats, *p_scale, *p_shift;
    int *p_rowptr, *p_cursor, *p_ekey, *p_bsums;
    float *p_enorm;
    unsigned int *p_whi, *p_wlo;
    cudaGetSymbolAddress((void**)&p_agg,  g_agg);
    cudaGetSymbolAddress((void**)&p_gi,   g_gi);
    cudaGetSymbolAddress((void**)&p_gh,   g_gh);
    cudaGetSymbolAddress((void**)&p_out,  g_out);
    cudaGetSymbolAddress((void**)&p_h,    g_h);
    cudaGetSymbolAddress((void**)&p_swh,  g_swh);
    cudaGetSymbolAddress((void**)&p_tmp,  g_tmp);
    cudaGetSymbolAddress((void**)&p_stats, g_stats);
    cudaGetSymbolAddress((void**)&p_scale, g_scale);
    cudaGetSymbolAddress((void**)&p_shift, g_shift);
    cudaGetSymbolAddress((void**)&p_rowptr, g_rowptr);
    cudaGetSymbolAddress((void**)&p_cursor, g_cursor);
    cudaGetSymbolAddress((void**)&p_ekey,  g_ekey);
    cudaGetSymbolAddress((void**)&p_enorm, g_enorm);
    cudaGetSymbolAddress((void**)&p_bsums, g_bsums);
    cudaGetSymbolAddress((void**)&p_whi,  g_whi);
    cudaGetSymbolAddress((void**)&p_wlo,  g_wlo);

    int mmgx = (NNODES + 127) / 128;               // 782
    const int NSCAN = (NNODES + 1023) / 1024;      // 98
    int aggrid = (NNODES * 32 + 255) / 256;

    // packed-weight unit bases
    unsigned int* whi_emb = p_whi;            unsigned int* wlo_emb = p_wlo;
    unsigned int* whi_rel = p_whi + 1 * 2048; unsigned int* wlo_rel = p_wlo + 1 * 2048;
    unsigned int* whi_ih  = p_whi + 4 * 2048; unsigned int* wlo_ih  = p_wlo + 4 * 2048;
    unsigned int* whi_hh  = p_whi + 7 * 2048; unsigned int* wlo_hh  = p_wlo + 7 * 2048;
    unsigned int* whi_a   = p_whi + 10 * 2048; unsigned int* wlo_a  = p_wlo + 10 * 2048;
    unsigned int* whi_b   = p_whi + 11 * 2048; unsigned int* wlo_b  = p_wlo + 11 * 2048;

    // launch #5 (counting the two memsets) is the embedding k_mm<1> for ncu
    cudaMemsetAsync(p_cursor, 0, NNODES * sizeof(int));                       // 0
    cudaMemsetAsync(p_stats, 0, 512 * sizeof(float));                         // 1
    k_packW<<<1, 256>>>(emb_W, 1, 0, 0, 1, whi_emb, wlo_emb);                 // 2
    k_count<<<(NEDGES + 255) / 256, 256>>>(dst, p_cursor);                    // 3
    k_scanA<<<NSCAN, 1024>>>(p_cursor, p_bsums);                              // 4
    k_mm<1><<<dim3(mmgx, 1), 256>>>(v, 64, whi_emb, wlo_emb, emb_b, 0,        // 5 PROFILED
                                    nullptr, nullptr, 0, p_out, 64, p_stats);
    k_scanB<<<1, 128>>>(p_bsums, NSCAN, p_rowptr);                            // 6
    k_finalize<<<1, 64>>>(p_stats, emb_g, emb_be, p_scale, p_shift);          // 7
    k_scanC<<<NSCAN, 1024>>>(p_cursor, p_bsums, p_rowptr, p_cursor);          // 8
    k_scatter<<<(NEDGES + 255) / 256, 256>>>(dst, src, rel, norm, p_cursor,   // 9
                                             p_ekey, p_enorm);
    // pack remaining weight families
    k_packW<<<3, 256>>>(relW, 0, 0, 4096, 3, whi_rel, wlo_rel);   // relW: 3 k-blocks
    k_packW<<<3, 256>>>(Wih, 1, 4096, 0, 1, whi_ih, wlo_ih);      // Wih: 3 y-blocks
    k_packW<<<3, 256>>>(Whh, 1, 4096, 0, 1, whi_hh, wlo_hh);      // Whh: 3 y-blocks
    k_packW<<<1, 256>>>(aW1, 1, 0, 0, 1, whi_a, wlo_a);
    k_packW<<<1, 256>>>(bW1, 1, 0, 0, 1, whi_b, wlo_b);

    // ---- layer 0: aggregate(relu(bn(emb))) -> 192->64 mm -> gi mm -> gates ----
    k_aggregate<1><<<aggrid, 256>>>(p_out, p_rowptr, p_ekey, p_enorm,
                                    p_scale, p_shift, p_agg);
    k_mm<3><<<dim3(mmgx, 1), 256>>>(p_agg, 192, whi_rel, wlo_rel, nullptr, 0,
                                    nullptr, nullptr, 0, p_swh, 64, nullptr);
    k_mm<1><<<dim3(mmgx, 3), 256>>>(p_swh, 64, whi_ih, wlo_ih, bih, 64,
                                    nullptr, nullptr, 0, p_gi, 192, nullptr);
    k_gates0<<<25000, 256>>>(p_gi, bhh, p_h);

    // ---- layer 1 ----
    k_aggregate<0><<<aggrid, 256>>>(p_h, p_rowptr, p_ekey, p_enorm,
                                    nullptr, nullptr, p_agg);
    k_mm<3><<<dim3(mmgx, 1), 256>>>(p_agg, 192, whi_rel, wlo_rel, nullptr, 0,
                                    nullptr, nullptr, 0, p_swh, 64, nullptr);
    k_mm<1><<<dim3(mmgx, 3), 256>>>(p_swh, 64, whi_ih, wlo_ih, bih, 64,
                                    nullptr, nullptr, 0, p_gi, 192, nullptr);
    k_mm<1><<<dim3(mmgx, 3), 256>>>(p_h, 64, whi_hh, wlo_hh, bhh, 64,
                                    nullptr, nullptr, 0, p_gh, 192, nullptr);
    k_gates<<<25000, 256>>>(p_gi, p_gh, p_h);

    // ---- kernel BN on h ----
    k_stats64<<<256, dim3(64, 4)>>>(p_h, p_stats + 128);
    k_finalize<<<1, 64>>>(p_stats + 128, ker_g, ker_be, p_scale + 64, p_shift + 64);

    // ---- head A ----
    k_mm<1><<<dim3(mmgx, 1), 256>>>(p_h, 64, whi_a, wlo_a, ab1, 0,
                                    p_scale + 64, p_shift + 64, 1, p_tmp, 64,
                                    p_stats + 256);
    k_finalize<<<1, 64>>>(p_stats + 256, ag, abe, p_scale + 128, p_shift + 128);
    k_head<2><<<12500, 256>>>(p_tmp, p_scale + 128, p_shift + 128, aW2, ab2, out);

    // ---- head B ----
    k_mm<1><<<dim3(mmgx, 1), 256>>>(p_h, 64, whi_b, wlo_b, bb1, 0,
                                    p_scale + 64, p_shift + 64, 1, p_tmp, 64,
                                    p_stats + 384);
    k_finalize<<<1, 64>>>(p_stats + 384, bg, bbe, p_scale + 192, p_shift + 192);
    k_head<21><<<12500, 256>>>(p_tmp, p_scale + 192, p_shift + 192, bW2, bb2,
                               out + (size_t)NNODES * 2);
}

// round 14
// speedup vs baseline: 1.4127x; 1.4127x over previous
#include <cuda_runtime.h>
#include <math.h>

#define NNODES 100000
#define NEDGES 1600000

// ---------------- scratch (static device globals; no allocations) ----------------
__device__ float g_agg [(size_t)NNODES * 192];
__device__ float g_gi  [(size_t)NNODES * 192];
__device__ float g_gh  [(size_t)NNODES * 192];
__device__ float g_out [(size_t)NNODES * 64];
__device__ float g_h   [(size_t)NNODES * 64];
__device__ float g_swh [(size_t)NNODES * 64];
__device__ float g_tmp [(size_t)NNODES * 64];
__device__ float g_stats[512];
__device__ float g_scale[4 * 64];
__device__ float g_shift[4 * 64];
__device__ int   g_rowptr[NNODES + 1];
__device__ int   g_cursor[NNODES];
__device__ int   g_ekey [NEDGES];
__device__ float g_enorm[NEDGES];
__device__ int   g_bsums[128];
// packed weights, stride-36 smem-ready layout: unit = 2304 uints (64 rows x 36).
// unit order: emb=0, relW=1..3, Wih=4..6, Whh=7..9, aW1=10, bW1=11
__device__ unsigned int g_whi[12 * 2304];
__device__ unsigned int g_wlo[12 * 2304];

__device__ __forceinline__ float sigm(float x) { return 1.0f / (1.0f + expf(-x)); }

__device__ __forceinline__ unsigned int packbf(float lo, float hi) {
    unsigned int r;
    asm("cvt.rn.bf16x2.f32 %0, %1, %2;" : "=r"(r) : "f"(hi), "f"(lo));
    return r;
}

#define MMA_BF16(c0, c1, c2, c3, a0, a1, a2, a3, b0, b1)                       \
    asm("mma.sync.aligned.m16n8k16.row.col.f32.bf16.bf16.f32 "                 \
        "{%0,%1,%2,%3}, {%4,%5,%6,%7}, {%8,%9}, {%0,%1,%2,%3};"                \
        : "+f"(c0), "+f"(c1), "+f"(c2), "+f"(c3)                               \
        : "r"(a0), "r"(a1), "r"(a2), "r"(a3), "r"(b0), "r"(b1))

// ---------------- weight pre-pack: 64x64 fp32 -> [n*36 + kpair] hi/lo ----------
__global__ void k_packW(const float* __restrict__ W, int transW,
                        int w_y_stride, int w_k_stride, int nkb,
                        unsigned int* __restrict__ hi, unsigned int* __restrict__ lo) {
    int u = blockIdx.x;
    int y = u / nkb, kb = u % nkb;
    const float* Wb = W + (size_t)y * w_y_stride + (size_t)kb * w_k_stride;
    for (int i = threadIdx.x; i < 2048; i += 256) {
        int n = i >> 5, p = i & 31;
        float f0, f1;
        if (transW) { f0 = Wb[n * 64 + 2 * p];   f1 = Wb[n * 64 + 2 * p + 1]; }
        else        { f0 = Wb[(2 * p) * 64 + n]; f1 = Wb[(2 * p + 1) * 64 + n]; }
        unsigned int h = packbf(f0, f1);
        float la = f0 - __uint_as_float(h << 16);
        float lb = f1 - __uint_as_float(h & 0xffff0000u);
        size_t o = (size_t)blockIdx.x * 2304 + n * 36 + p;
        hi[o] = h;
        lo[o] = packbf(la, lb);
    }
    // zero the 4-uint pad per row so uint4 copies stay defined
    for (int i = threadIdx.x; i < 256; i += 256) {
        int n = i >> 2, p = 32 + (i & 3);
        size_t o = (size_t)blockIdx.x * 2304 + n * 36 + p;
        hi[o] = 0u; lo[o] = 0u;
    }
}

// ---------------- CSR build ----------------
__global__ void k_count(const int* __restrict__ dst, int* __restrict__ cnt) {
    int e = blockIdx.x * blockDim.x + threadIdx.x;
    if (e < NEDGES) atomicAdd(&cnt[dst[e]], 1);
}

__global__ void k_scanA(const int* __restrict__ cnt, int* __restrict__ bsums) {
    __shared__ int sh[1024];
    int i = blockIdx.x * 1024 + threadIdx.x;
    sh[threadIdx.x] = (i < NNODES) ? cnt[i] : 0;
    __syncthreads();
    for (int off = 512; off > 0; off >>= 1) {
        if (threadIdx.x < off) sh[threadIdx.x] += sh[threadIdx.x + off];
        __syncthreads();
    }
    if (threadIdx.x == 0) bsums[blockIdx.x] = sh[0];
}

__global__ void k_scanB(int* __restrict__ bsums, int nb, int* __restrict__ rowptr) {
    __shared__ int sh[128];
    int t = threadIdx.x;
    int orig = (t < nb) ? bsums[t] : 0;
    sh[t] = orig;
    __syncthreads();
    for (int off = 1; off < 128; off <<= 1) {
        int v = (t >= off) ? sh[t - off] : 0;
        __syncthreads();
        sh[t] += v;
        __syncthreads();
    }
    if (t < nb) bsums[t] = sh[t] - orig;
    if (t == 0) rowptr[NNODES] = NEDGES;
}

__global__ void k_scanC(int* __restrict__ cnt, const int* __restrict__ bsums,
                        int* __restrict__ rowptr, int* __restrict__ cursor) {
    __shared__ int sh[1024];
    int i = blockIdx.x * 1024 + threadIdx.x;
    int orig = (i < NNODES) ? cnt[i] : 0;
    sh[threadIdx.x] = orig;
    __syncthreads();
    for (int off = 1; off < 1024; off <<= 1) {
        int v = (threadIdx.x >= off) ? sh[threadIdx.x - off] : 0;
        __syncthreads();
        sh[threadIdx.x] += v;
        __syncthreads();
    }
    if (i < NNODES) {
        int start = bsums[blockIdx.x] + sh[threadIdx.x] - orig;
        rowptr[i] = start;
        cursor[i] = start;
    }
}

__global__ void k_scatter(const int* __restrict__ dst, const int* __restrict__ src,
                          const int* __restrict__ rel, const float* __restrict__ norm,
                          int* __restrict__ cursor,
                          int* __restrict__ ekey, float* __restrict__ enorm) {
    int e = blockIdx.x * blockDim.x + threadIdx.x;
    if (e < NEDGES) {
        int pos = atomicAdd(&cursor[dst[e]], 1);
        ekey[pos]  = (src[e] << 2) | rel[e];
        enorm[pos] = norm[e];
    }
}

// ---------------- tensor-core matmul: 64 nodes x NY*64 cols, pre-packed W ------
// R12 geometry: 256 threads, warp w: m-tile (w&3)*16, n-half (w>>2)*32.
// A staged+packed once (NY>1 requires KB==1); W copied per unit via uint4.
// Split: D ~= AhBh + AhBl + AlBh.
template <int KB, int NY>
__global__ __launch_bounds__(256) void k_mm(
    const float* __restrict__ A, int a_stride,
    const unsigned int* __restrict__ Whig, const unsigned int* __restrict__ Wlog,
    const float* __restrict__ bias, int bias_blk,
    const float* __restrict__ in_scale, const float* __restrict__ in_shift, int in_act,
    float* __restrict__ C, int c_stride,
    float* __restrict__ stats)
{
    __shared__ unsigned int Ahi[64 * 36], Alo[64 * 36];
    __shared__ unsigned int Whi[64 * 36], Wlo[64 * 36];   // 36,864 B

    int tid  = threadIdx.x;
    int warp = tid >> 5, lane = tid & 31;
    int gid  = lane >> 2, tig = lane & 3;
    int wm   = warp & 3;
    int wn   = warp >> 2;
    int nbase = blockIdx.x * 64;

    float s_loc[8], q_loc[8];
#pragma unroll
    for (int e = 0; e < 8; e++) { s_loc[e] = 0.f; q_loc[e] = 0.f; }

#pragma unroll
    for (int y = 0; y < NY; y++) {
        float acc[4][4];
#pragma unroll
        for (int nt = 0; nt < 4; nt++)
#pragma unroll
            for (int q = 0; q < 4; q++) acc[nt][q] = 0.f;

#pragma unroll
        for (int kb = 0; kb < KB; kb++) {
            if (y > 0 || kb > 0) __syncthreads();

            // stage A for this kb (NY>1 implies KB==1, so only at y==0)
            if (y == 0) {
                for (int i = tid; i < 1024; i += 256) {
                    int r = i >> 4, c4 = i & 15;
                    float4 v = make_float4(0.f, 0.f, 0.f, 0.f);
                    int gn = nbase + r;
                    if (gn < NNODES)
                        v = reinterpret_cast<const float4*>(
                                A + (size_t)gn * a_stride + kb * 64)[c4];
                    if (in_act) {
                        int c = c4 * 4;
                        v.x = v.x * in_scale[c]     + in_shift[c];
                        v.y = v.y * in_scale[c + 1] + in_shift[c + 1];
                        v.z = v.z * in_scale[c + 2] + in_shift[c + 2];
                        v.w = v.w * in_scale[c + 3] + in_shift[c + 3];
                    }
                    unsigned int h0 = packbf(v.x, v.y);
                    unsigned int h1 = packbf(v.z, v.w);
                    float l0a = v.x - __uint_as_float(h0 << 16);
                    float l0b = v.y - __uint_as_float(h0 & 0xffff0000u);
                    float l1a = v.z - __uint_as_float(h1 << 16);
                    float l1b = v.w - __uint_as_float(h1 & 0xffff0000u);
                    int base = r * 36 + c4 * 2;
                    Ahi[base]     = h0;
                    Ahi[base + 1] = h1;
                    Alo[base]     = packbf(l0a, l0b);
                    Alo[base + 1] = packbf(l1a, l1b);
                }
            }

            // copy pre-packed W unit (stride-36, uint4)
            {
                const uint4* HG = reinterpret_cast<const uint4*>(
                    Whig + (size_t)(y * KB + kb) * 2304);
                const uint4* LG = reinterpret_cast<const uint4*>(
                    Wlog + (size_t)(y * KB + kb) * 2304);
                uint4* HS = reinterpret_cast<uint4*>(Whi);
                uint4* LS = reinterpret_cast<uint4*>(Wlo);
                for (int i = tid; i < 576; i += 256) {
                    HS[i] = HG[i];
                    LS[i] = LG[i];
                }
            }
            __syncthreads();

            int r0 = wm * 16 + gid;
#pragma unroll
            for (int ks = 0; ks < 4; ks++) {
                int kp = ks * 8;
                unsigned int ah0 = Ahi[r0 * 36 + kp + tig];
                unsigned int ah1 = Ahi[(r0 + 8) * 36 + kp + tig];
                unsigned int ah2 = Ahi[r0 * 36 + kp + tig + 4];
                unsigned int ah3 = Ahi[(r0 + 8) * 36 + kp + tig + 4];
                unsigned int al0 = Alo[r0 * 36 + kp + tig];
                unsigned int al1 = Alo[(r0 + 8) * 36 + kp + tig];
                unsigned int al2 = Alo[r0 * 36 + kp + tig + 4];
                unsigned int al3 = Alo[(r0 + 8) * 36 + kp + tig + 4];
#pragma unroll
                for (int nt = 0; nt < 4; nt++) {
                    int n0 = wn * 32 + nt * 8 + gid;
                    unsigned int bh0 = Whi[n0 * 36 + kp + tig];
                    unsigned int bh1 = Whi[n0 * 36 + kp + tig + 4];
                    unsigned int bl0 = Wlo[n0 * 36 + kp + tig];
                    unsigned int bl1 = Wlo[n0 * 36 + kp + tig + 4];
                    MMA_BF16(acc[nt][0], acc[nt][1], acc[nt][2], acc[nt][3],
                             ah0, ah1, ah2, ah3, bh0, bh1);
                    MMA_BF16(acc[nt][0], acc[nt][1], acc[nt][2], acc[nt][3],
                             ah0, ah1, ah2, ah3, bl0, bl1);
                    MMA_BF16(acc[nt][0], acc[nt][1], acc[nt][2], acc[nt][3],
                             al0, al1, al2, al3, bh0, bh1);
                }
            }
        }

        // ---- epilogue for this y ----
        int row0 = nbase + wm * 16 + gid;
        int row1 = row0 + 8;
#pragma unroll
        for (int nt = 0; nt < 4; nt++) {
            int lcol = wn * 32 + nt * 8 + 2 * tig;
            int gcol = y * 64 + lcol;
            float bv0 = 0.f, bv1 = 0.f;
            if (bias) {
                const float* bb = bias + y * bias_blk;
                bv0 = bb[lcol]; bv1 = bb[lcol + 1];
            }
            float o00 = acc[nt][0] + bv0, o01 = acc[nt][1] + bv1;
            float o10 = acc[nt][2] + bv0, o11 = acc[nt][3] + bv1;
            if (row0 < NNODES) {
                *reinterpret_cast<float2*>(C + (size_t)row0 * c_stride + gcol) =
                    make_float2(o00, o01);
                s_loc[nt * 2]     += o00; q_loc[nt * 2]     += o00 * o00;
                s_loc[nt * 2 + 1] += o01; q_loc[nt * 2 + 1] += o01 * o01;
            }
            if (row1 < NNODES) {
                *reinterpret_cast<float2*>(C + (size_t)row1 * c_stride + gcol) =
                    make_float2(o10, o11);
                s_loc[nt * 2]     += o10; q_loc[nt * 2]     += o10 * o10;
                s_loc[nt * 2 + 1] += o11; q_loc[nt * 2 + 1] += o11 * o11;
            }
        }
    }

    if (stats) {   // only used with NY==1
        __syncthreads();
        float* ssum = reinterpret_cast<float*>(Ahi);
        float* ssq  = ssum + 64;
        if (tid < 128) ssum[tid] = 0.f;
        __syncthreads();
#pragma unroll
        for (int nt = 0; nt < 4; nt++) {
            int lcol = wn * 32 + nt * 8 + 2 * tig;
            atomicAdd(&ssum[lcol],     s_loc[nt * 2]);
            atomicAdd(&ssum[lcol + 1], s_loc[nt * 2 + 1]);
            atomicAdd(&ssq [lcol],     q_loc[nt * 2]);
            atomicAdd(&ssq [lcol + 1], q_loc[nt * 2 + 1]);
        }
        __syncthreads();
        if (tid < 64) {
            atomicAdd(&stats[tid], ssum[tid]);
            atomicAdd(&stats[64 + tid], ssq[tid]);
        }
    }
}

// ---------------- BN helpers ----------------
__global__ void k_finalize(const float* __restrict__ stats, const float* __restrict__ gamma,
                           const float* __restrict__ beta, float* __restrict__ scale,
                           float* __restrict__ shift) {
    int k = threadIdx.x;
    const float invN = 1.0f / (float)NNODES;
    float mean = stats[k] * invN;
    float var = stats[64 + k] * invN - mean * mean;
    float sc = gamma[k] * rsqrtf(var + 1e-5f);
    scale[k] = sc;
    shift[k] = beta[k] - mean * sc;
}

__global__ void k_stats64(const float* __restrict__ X, float* __restrict__ stats) {
    __shared__ float ssum[64], ssq[64];
    int k = threadIdx.x, ty = threadIdx.y;
    if (ty == 0) { ssum[k] = 0.f; ssq[k] = 0.f; }
    __syncthreads();
    float s = 0.f, q = 0.f;
    for (int n = blockIdx.x * 4 + ty; n < NNODES; n += gridDim.x * 4) {
        float v = X[(size_t)n * 64 + k];
        s += v; q += v * v;
    }
    atomicAdd(&ssum[k], s); atomicAdd(&ssq[k], q);
    __syncthreads();
    if (ty == 0) { atomicAdd(&stats[k], ssum[k]); atomicAdd(&stats[64 + k], ssq[k]); }
}

// ---------------- rel-split edge aggregation (warp per node) ----------------
template <int AFF>
__global__ void k_aggregate(const float* __restrict__ in, const int* __restrict__ rowptr,
                            const int* __restrict__ ekey, const float* __restrict__ enorm,
                            const float* __restrict__ scale, const float* __restrict__ shift,
                            float* __restrict__ agg) {
    int node = (blockIdx.x * blockDim.x + threadIdx.x) >> 5;
    int lane = threadIdx.x & 31;
    if (node >= NNODES) return;
    float sc0 = 1.f, sc1 = 1.f, sf0 = 0.f, sf1 = 0.f;
    if (AFF) { sc0 = scale[lane]; sc1 = scale[lane + 32];
               sf0 = shift[lane]; sf1 = shift[lane + 32]; }
    int beg = rowptr[node], end = rowptr[node + 1];
    float a00 = 0.f, a01 = 0.f, a10 = 0.f, a11 = 0.f, a20 = 0.f, a21 = 0.f;
    for (int e = beg; e < end; ++e) {
        int k0 = ekey[e];
        float w = enorm[e];
        const float* row = in + (size_t)(k0 >> 2) * 64;
        float v0 = row[lane], v1 = row[lane + 32];
        if (AFF) {
            v0 = fmaxf(v0 * sc0 + sf0, 0.f);
            v1 = fmaxf(v1 * sc1 + sf1, 0.f);
        }
        int r = k0 & 3;
        if (r == 0)      { a00 = fmaf(v0, w, a00); a01 = fmaf(v1, w, a01); }
        else if (r == 1) { a10 = fmaf(v0, w, a10); a11 = fmaf(v1, w, a11); }
        else             { a20 = fmaf(v0, w, a20); a21 = fmaf(v1, w, a21); }
    }
    float* o = agg + (size_t)node * 192;
    o[lane] = a00;       o[lane + 32] = a01;
    o[64 + lane] = a10;  o[96 + lane] = a11;
    o[128 + lane] = a20; o[160 + lane] = a21;
}

// ---------------- GRU gate fusion ----------------
__global__ void k_gates0(const float* __restrict__ gi, const float* __restrict__ bhh,
                         float* __restrict__ h) {
    size_t idx = (size_t)blockIdx.x * blockDim.x + threadIdx.x;
    if (idx >= (size_t)NNODES * 64) return;
    int n = (int)(idx >> 6), k = (int)(idx & 63);
    size_t b = (size_t)n * 192;
    float r = sigm(gi[b + k] + bhh[k]);
    float z = sigm(gi[b + 64 + k] + bhh[64 + k]);
    float nn = tanhf(gi[b + 128 + k] + r * bhh[128 + k]);
    h[idx] = (1.0f - z) * nn;
}

__global__ void k_gates(const float* __restrict__ gi, const float* __restrict__ gh,
                        float* __restrict__ h) {
    size_t idx = (size_t)blockIdx.x * blockDim.x + threadIdx.x;
    if (idx >= (size_t)NNODES * 64) return;
    int n = (int)(idx >> 6), k = (int)(idx & 63);
    size_t b = (size_t)n * 192;
    float r = sigm(gi[b + k] + gh[b + k]);
    float z = sigm(gi[b + 64 + k] + gh[b + 64 + k]);
    float nn = tanhf(gi[b + 128 + k] + r * gh[b + 128 + k]);
    float hv = h[idx];
    h[idx] = (1.0f - z) * nn + z * hv;
}

// ---------------- head output: relu(BN(tmp)) @ W2.T + b2 ----------------
template <int KO>
__global__ void k_head(const float* __restrict__ X, const float* __restrict__ scale,
                       const float* __restrict__ shift, const float* __restrict__ W2,
                       const float* __restrict__ b2, float* __restrict__ out) {
    __shared__ float Wsh[KO * 65];
    __shared__ float sc[64], sf[64];
    int tid = threadIdx.x;
    for (int i = tid; i < KO * 64; i += 256) {
        int k = i >> 6, d = i & 63;
        Wsh[k * 65 + d] = W2[i];
    }
    if (tid < 64) { sc[tid] = scale[tid]; sf[tid] = shift[tid]; }
    __syncthreads();
    int warp = tid >> 5, lane = tid & 31;
    int n = blockIdx.x * 8 + warp;
    if (n >= NNODES) return;
    float acc = (lane < KO) ? b2[lane] : 0.f;
    const float* row = X + (size_t)n * 64;
    for (int d = 0; d < 64; d++) {
        float x = fmaxf(row[d] * sc[d] + sf[d], 0.f);
        if (lane < KO) acc = fmaf(x, Wsh[lane * 65 + d], acc);
    }
    if (lane < KO) out[(size_t)n * KO + lane] = acc;
}

// ---------------- launch ----------------
extern "C" void kernel_launch(void* const* d_in, const int* in_sizes, int n_in,
                              void* d_out, int out_size) {
    const float* v      = (const float*)d_in[0];
    const int*   src    = (const int*)d_in[1];
    const int*   dst    = (const int*)d_in[2];
    const int*   rel    = (const int*)d_in[3];
    const float* norm   = (const float*)d_in[4];
    const float* emb_W  = (const float*)d_in[5];
    const float* emb_b  = (const float*)d_in[6];
    const float* emb_g  = (const float*)d_in[7];
    const float* emb_be = (const float*)d_in[8];
    const float* relW   = (const float*)d_in[9];
    const float* Wih    = (const float*)d_in[10];
    const float* Whh    = (const float*)d_in[11];
    const float* bih    = (const float*)d_in[12];
    const float* bhh    = (const float*)d_in[13];
    const float* ker_g  = (const float*)d_in[14];
    const float* ker_be = (const float*)d_in[15];
    const float* aW1 = (const float*)d_in[16];
    const float* ab1 = (const float*)d_in[17];
    const float* ag  = (const float*)d_in[18];
    const float* abe = (const float*)d_in[19];
    const float* aW2 = (const float*)d_in[20];
    const float* ab2 = (const float*)d_in[21];
    const float* bW1 = (const float*)d_in[22];
    const float* bb1 = (const float*)d_in[23];
    const float* bg  = (const float*)d_in[24];
    const float* bbe = (const float*)d_in[25];
    const float* bW2 = (const float*)d_in[26];
    const float* bb2 = (const float*)d_in[27];
    float* out = (float*)d_out;

    float *p_agg, *p_gi, *p_gh, *p_out, *p_h, *p_swh, *p_tmp, *p_stats, *p_scale, *p_shift;
    int *p_rowptr, *p_cursor, *p_ekey, *p_bsums;
    float *p_enorm;
    unsigned int *p_whi, *p_wlo;
    cudaGetSymbolAddress((void**)&p_agg,  g_agg);
    cudaGetSymbolAddress((void**)&p_gi,   g_gi);
    cudaGetSymbolAddress((void**)&p_gh,   g_gh);
    cudaGetSymbolAddress((void**)&p_out,  g_out);
    cudaGetSymbolAddress((void**)&p_h,    g_h);
    cudaGetSymbolAddress((void**)&p_swh,  g_swh);
    cudaGetSymbolAddress((void**)&p_tmp,  g_tmp);
    cudaGetSymbolAddress((void**)&p_stats, g_stats);
    cudaGetSymbolAddress((void**)&p_scale, g_scale);
    cudaGetSymbolAddress((void**)&p_shift, g_shift);
    cudaGetSymbolAddress((void**)&p_rowptr, g_rowptr);
    cudaGetSymbolAddress((void**)&p_cursor, g_cursor);
    cudaGetSymbolAddress((void**)&p_ekey,  g_ekey);
    cudaGetSymbolAddress((void**)&p_enorm, g_enorm);
    cudaGetSymbolAddress((void**)&p_bsums, g_bsums);
    cudaGetSymbolAddress((void**)&p_whi,  g_whi);
    cudaGetSymbolAddress((void**)&p_wlo,  g_wlo);

    int mmgx = (NNODES + 63) / 64;                 // 1563
    const int NSCAN = (NNODES + 1023) / 1024;      // 98
    int aggrid = (NNODES * 32 + 255) / 256;

    unsigned int* whi_emb = p_whi;             unsigned int* wlo_emb = p_wlo;
    unsigned int* whi_rel = p_whi + 1 * 2304;  unsigned int* wlo_rel = p_wlo + 1 * 2304;
    unsigned int* whi_ih  = p_whi + 4 * 2304;  unsigned int* wlo_ih  = p_wlo + 4 * 2304;
    unsigned int* whi_hh  = p_whi + 7 * 2304;  unsigned int* wlo_hh  = p_wlo + 7 * 2304;
    unsigned int* whi_a   = p_whi + 10 * 2304; unsigned int* wlo_a   = p_wlo + 10 * 2304;
    unsigned int* whi_b   = p_whi + 11 * 2304; unsigned int* wlo_b   = p_wlo + 11 * 2304;

    // launch #5 (counting the two memsets) is the embedding k_mm for ncu
    cudaMemsetAsync(p_cursor, 0, NNODES * sizeof(int));                       // 0
    cudaMemsetAsync(p_stats, 0, 512 * sizeof(float));                         // 1
    k_packW<<<1, 256>>>(emb_W, 1, 0, 0, 1, whi_emb, wlo_emb);                 // 2
    k_count<<<(NEDGES + 255) / 256, 256>>>(dst, p_cursor);                    // 3
    k_scanA<<<NSCAN, 1024>>>(p_cursor, p_bsums);                              // 4
    k_mm<1, 1><<<mmgx, 256>>>(v, 64, whi_emb, wlo_emb, emb_b, 0,              // 5 PROFILED
                              nullptr, nullptr, 0, p_out, 64, p_stats);
    k_scanB<<<1, 128>>>(p_bsums, NSCAN, p_rowptr);                            // 6
    k_finalize<<<1, 64>>>(p_stats, emb_g, emb_be, p_scale, p_shift);          // 7
    k_scanC<<<NSCAN, 1024>>>(p_cursor, p_bsums, p_rowptr, p_cursor);          // 8
    k_scatter<<<(NEDGES + 255) / 256, 256>>>(dst, src, rel, norm, p_cursor,   // 9
                                             p_ekey, p_enorm);
    k_packW<<<3, 256>>>(relW, 0, 0, 4096, 3, whi_rel, wlo_rel);
    k_packW<<<3, 256>>>(Wih, 1, 4096, 0, 1, whi_ih, wlo_ih);
    k_packW<<<3, 256>>>(Whh, 1, 4096, 0, 1, whi_hh, wlo_hh);
    k_packW<<<1, 256>>>(aW1, 1, 0, 0, 1, whi_a, wlo_a);
    k_packW<<<1, 256>>>(bW1, 1, 0, 0, 1, whi_b, wlo_b);

    // ---- layer 0 ----
    k_aggregate<1><<<aggrid, 256>>>(p_out, p_rowptr, p_ekey, p_enorm,
                                    p_scale, p_shift, p_agg);
    k_mm<3, 1><<<mmgx, 256>>>(p_agg, 192, whi_rel, wlo_rel, nullptr, 0,
                              nullptr, nullptr, 0, p_swh, 64, nullptr);
    k_mm<1, 3><<<mmgx, 256>>>(p_swh, 64, whi_ih, wlo_ih, bih, 64,
                              nullptr, nullptr, 0, p_gi, 192, nullptr);
    k_gates0<<<25000, 256>>>(p_gi, bhh, p_h);

    // ---- layer 1 ----
    k_aggregate<0><<<aggrid, 256>>>(p_h, p_rowptr, p_ekey, p_enorm,
                                    nullptr, nullptr, p_agg);
    k_mm<3, 1><<<mmgx, 256>>>(p_agg, 192, whi_rel, wlo_rel, nullptr, 0,
                              nullptr, nullptr, 0, p_swh, 64, nullptr);
    k_mm<1, 3><<<mmgx, 256>>>(p_swh, 64, whi_ih, wlo_ih, bih, 64,
                              nullptr, nullptr, 0, p_gi, 192, nullptr);
    k_mm<1, 3><<<mmgx, 256>>>(p_h, 64, whi_hh, wlo_hh, bhh, 64,
                              nullptr, nullptr, 0, p_gh, 192, nullptr);
    k_gates<<<25000, 256>>>(p_gi, p_gh, p_h);

    // ---- kernel BN on h ----
    k_stats64<<<256, dim3(64, 4)>>>(p_h, p_stats + 128);
    k_finalize<<<1, 64>>>(p_stats + 128, ker_g, ker_be, p_scale + 64, p_shift + 64);

    // ---- head A ----
    k_mm<1, 1><<<mmgx, 256>>>(p_h, 64, whi_a, wlo_a, ab1, 0,
                              p_scale + 64, p_shift + 64, 1, p_tmp, 64,
                              p_stats + 256);
    k_finalize<<<1, 64>>>(p_stats + 256, ag, abe, p_scale + 128, p_shift + 128);
    k_head<2><<<12500, 256>>>(p_tmp, p_scale + 128, p_shift + 128, aW2, ab2, out);

    // ---- head B ----
    k_mm<1, 1><<<mmgx, 256>>>(p_h, 64, whi_b, wlo_b, bb1, 0,
                              p_scale + 64, p_shift + 64, 1, p_tmp, 64,
                              p_stats + 384);
    k_finalize<<<1, 64>>>(p_stats + 384, bg, bbe, p_scale + 192, p_shift + 192);
    k_head<21><<<12500, 256>>>(p_tmp, p_scale + 192, p_shift + 192, bW2, bb2,
                               out + (size_t)NNODES * 2);
}